// round 7
// baseline (speedup 1.0000x reference)
#include <cuda_runtime.h>
#include <cuda_bf16.h>
#include <math.h>

#define B_  16
#define T_  512
#define C_  256
#define H_  8
#define HST 32
#define HSS 64

#define N_BTC (B_*T_*C_)                 // 2,097,152
#define N_FF  (B_*T_*4*C_)               // 8,388,608
#define N_SCT ((long long)B_*H_*T_*T_)   // 33,554,432
#define N_SCS ((long long)B_*H_*C_*C_)   // 8,388,608
#define N_CC  (B_*C_*C_)                 // 1,048,576

// ---------------- fp32 scratch ----------------
#define FF_scT  0LL
#define FF_scS  (FF_scT + N_SCT)
#define FF_xb   (FF_scS + N_SCS)
#define FF_x2b  (FF_xb  + N_BTC)
#define FF_tout (FF_x2b + N_BTC)
#define FF_TOT  (FF_tout + N_BTC)
__device__ float g_f[FF_TOT];

// ---------------- bf16 plane scratch (hi at off, lo at off+size) ----------
#define PP_h    0LL
#define PP_q    (PP_h    + 2*(long long)N_BTC)
#define PP_k    (PP_q    + 2*(long long)N_BTC)
#define PP_vT   (PP_k    + 2*(long long)N_BTC)
#define PP_att  (PP_vT   + 2*(long long)N_BTC)
#define PP_ob   (PP_att  + 2*N_SCT)
#define PP_h2   (PP_ob   + 2*(long long)N_BTC)
#define PP_ffb  (PP_h2   + 2*(long long)N_BTC)
#define PP_tout (PP_ffb  + 2*(long long)N_FF)
#define PP_hs   (PP_tout + 2*(long long)N_BTC)
#define PP_qs   (PP_hs   + 2*(long long)N_BTC)
#define PP_ks   (PP_qs   + 2*(long long)N_BTC)
#define PP_h3   (PP_ks   + 2*(long long)N_BTC)
#define PP_sw   (PP_h3   + 2*(long long)N_BTC)
#define PP_wqt  (PP_sw   + 2*(long long)N_CC)
#define PP_wkt  (PP_wqt  + 2*65536LL)
#define PP_wvt  (PP_wkt  + 2*65536LL)
#define PP_wo   (PP_wvt  + 2*65536LL)
#define PP_wqs  (PP_wo   + 2*65536LL)
#define PP_wks  (PP_wqs  + 2*262144LL)
#define PP_f1w1 (PP_wks  + 2*262144LL)
#define PP_f1w2 (PP_f1w1 + 2*262144LL)
#define PP_f2w1 (PP_f1w2 + 2*262144LL)
#define PP_f2w2 (PP_f2w1 + 2*262144LL)
#define PP_TOT  (PP_f2w2 + 2*262144LL)
__device__ __nv_bfloat16 g_p[PP_TOT];

// ============================ helpers ======================================
__device__ __forceinline__ void split1(float x, __nv_bfloat16 &h, __nv_bfloat16 &l) {
    h = __float2bfloat16_rn(x);
    l = __float2bfloat16_rn(x - __bfloat162float(h));
}
__device__ __forceinline__ void split2v(float x0, float x1, __nv_bfloat162 &hi, __nv_bfloat162 &lo) {
    hi = __floats2bfloat162_rn(x0, x1);
    lo = __floats2bfloat162_rn(x0 - __bfloat162float(hi.x), x1 - __bfloat162float(hi.y));
}
__device__ __forceinline__ void cpasync16(unsigned d, const void* s) {
    asm volatile("cp.async.cg.shared.global [%0], [%1], 16;" :: "r"(d), "l"(s) : "memory");
}
__device__ __forceinline__ void cp_commit() { asm volatile("cp.async.commit_group;" ::: "memory"); }
template<int N> __device__ __forceinline__ void cp_wait() {
    asm volatile("cp.async.wait_group %0;" :: "n"(N) : "memory");
}
__device__ __forceinline__ void ldm4(unsigned &r0, unsigned &r1, unsigned &r2, unsigned &r3, unsigned a) {
    asm volatile("ldmatrix.sync.aligned.m8n8.x4.shared.b16 {%0,%1,%2,%3}, [%4];"
        : "=r"(r0), "=r"(r1), "=r"(r2), "=r"(r3) : "r"(a));
}
__device__ __forceinline__ void mma16(float* c, const unsigned* a, const unsigned* b) {
    asm volatile("mma.sync.aligned.m16n8k16.row.col.f32.bf16.bf16.f32 "
        "{%0,%1,%2,%3}, {%4,%5,%6,%7}, {%8,%9}, {%0,%1,%2,%3};"
        : "+f"(c[0]), "+f"(c[1]), "+f"(c[2]), "+f"(c[3])
        : "r"(a[0]), "r"(a[1]), "r"(a[2]), "r"(a[3]), "r"(b[0]), "r"(b[1]));
}

// ====================== elementwise kernels ================================
__global__ void split_kernel(const float* __restrict__ x,
                             __nv_bfloat16* __restrict__ ph, __nv_bfloat16* __restrict__ pl, int n4) {
    int i = blockIdx.x * 256 + threadIdx.x;
    if (i >= n4) return;
    float4 v = reinterpret_cast<const float4*>(x)[i];
    __nv_bfloat162 h0, l0, h1, l1;
    split2v(v.x, v.y, h0, l0);
    split2v(v.z, v.w, h1, l1);
    reinterpret_cast<__nv_bfloat162*>(ph)[2 * i]     = h0;
    reinterpret_cast<__nv_bfloat162*>(ph)[2 * i + 1] = h1;
    reinterpret_cast<__nv_bfloat162*>(pl)[2 * i]     = l0;
    reinterpret_cast<__nv_bfloat162*>(pl)[2 * i + 1] = l1;
}

__global__ void ln_planes_kernel(const float* __restrict__ x,
                                 __nv_bfloat16* __restrict__ ph, __nv_bfloat16* __restrict__ pl,
                                 const float* __restrict__ w, const float* __restrict__ b, int L) {
    long long base = (long long)blockIdx.x * L;
    int tid = threadIdx.x;
    float s = 0.f, s2 = 0.f;
    for (int i = tid; i < L; i += 256) {
        float v = x[base + i];
        s += v; s2 += v * v;
    }
    __shared__ float sh[64];
    #pragma unroll
    for (int o = 16; o > 0; o >>= 1) {
        s  += __shfl_down_sync(0xffffffffu, s,  o);
        s2 += __shfl_down_sync(0xffffffffu, s2, o);
    }
    int warp = tid >> 5, lane = tid & 31;
    if (lane == 0) { sh[warp] = s; sh[warp + 32] = s2; }
    __syncthreads();
    if (tid == 0) {
        float ts = 0.f, ts2 = 0.f;
        for (int i = 0; i < 8; i++) { ts += sh[i]; ts2 += sh[32 + i]; }
        float m = ts / (float)L;
        float var = ts2 / (float)L - m * m;
        sh[0] = m;
        sh[1] = rsqrtf(var + 1e-6f);
    }
    __syncthreads();
    float m = sh[0], r = sh[1];
    for (int i = tid; i < L; i += 256) {
        float y = (x[base + i] - m) * r * w[i] + b[i];
        __nv_bfloat16 h, l;
        split1(y, h, l);
        ph[base + i] = h;
        pl[base + i] = l;
    }
}

// spatial softmax, fp32 in-place, L<=512
__global__ void softmax_kernel(float* __restrict__ x, int L) {
    long long base = (long long)blockIdx.x * L;
    int tid = threadIdx.x;
    float v[2];
    #pragma unroll
    for (int c = 0; c < 2; c++) {
        int i = tid + c * 256;
        v[c] = (i < L) ? x[base + i] : -3.4e38f;
    }
    float mx = fmaxf(v[0], v[1]);
    __shared__ float sh[32];
    #pragma unroll
    for (int o = 16; o > 0; o >>= 1) mx = fmaxf(mx, __shfl_down_sync(0xffffffffu, mx, o));
    int warp = tid >> 5, lane = tid & 31;
    if (lane == 0) sh[warp] = mx;
    __syncthreads();
    if (tid == 0) {
        float m = sh[0];
        for (int i = 1; i < 8; i++) m = fmaxf(m, sh[i]);
        sh[0] = m;
    }
    __syncthreads();
    mx = sh[0];
    float sum = 0.f;
    #pragma unroll
    for (int c = 0; c < 2; c++) {
        int i = tid + c * 256;
        if (i < L) { v[c] = expf(v[c] - mx); sum += v[c]; }
    }
    __syncthreads();
    #pragma unroll
    for (int o = 16; o > 0; o >>= 1) sum += __shfl_down_sync(0xffffffffu, sum, o);
    if (lane == 0) sh[warp] = sum;
    __syncthreads();
    if (tid == 0) {
        float s = 0.f;
        for (int i = 0; i < 8; i++) s += sh[i];
        sh[0] = 1.f / s;
    }
    __syncthreads();
    float inv = sh[0];
    #pragma unroll
    for (int c = 0; c < 2; c++) {
        int i = tid + c * 256;
        if (i < L) x[base + i] = v[c] * inv;
    }
}

// causal softmax over rows of length T_: reads fp32, writes bf16 hi/lo planes
__global__ void softmax_causal_planes(const float* __restrict__ x,
                                      __nv_bfloat16* __restrict__ ph,
                                      __nv_bfloat16* __restrict__ pl) {
    long long base = (long long)blockIdx.x * T_;
    int t = blockIdx.x % T_;
    int tid = threadIdx.x;
    float v[2];
    bool act[2];
    #pragma unroll
    for (int c = 0; c < 2; c++) {
        int i = tid + c * 256;
        act[c] = (i <= t);
        v[c] = act[c] ? x[base + i] : -3.4e38f;
    }
    float mx = fmaxf(v[0], v[1]);
    __shared__ float sh[32];
    #pragma unroll
    for (int o = 16; o > 0; o >>= 1) mx = fmaxf(mx, __shfl_down_sync(0xffffffffu, mx, o));
    int warp = tid >> 5, lane = tid & 31;
    if (lane == 0) sh[warp] = mx;
    __syncthreads();
    if (tid == 0) {
        float m = sh[0];
        for (int i = 1; i < 8; i++) m = fmaxf(m, sh[i]);
        sh[0] = m;
    }
    __syncthreads();
    mx = sh[0];
    float sum = 0.f;
    #pragma unroll
    for (int c = 0; c < 2; c++) {
        if (act[c]) { v[c] = expf(v[c] - mx); sum += v[c]; }
    }
    __syncthreads();
    #pragma unroll
    for (int o = 16; o > 0; o >>= 1) sum += __shfl_down_sync(0xffffffffu, sum, o);
    if (lane == 0) sh[warp] = sum;
    __syncthreads();
    if (tid == 0) {
        float s = 0.f;
        for (int i = 0; i < 8; i++) s += sh[i];
        sh[0] = 1.f / s;
    }
    __syncthreads();
    float inv = sh[0];
    #pragma unroll
    for (int c = 0; c < 2; c++) {
        int i = tid + c * 256;
        float y = act[c] ? v[c] * inv : 0.f;
        __nv_bfloat16 h, l;
        split1(y, h, l);
        ph[base + i] = h;
        pl[base + i] = l;
    }
}

// mean over heads -> fp32 out + planes
__global__ void mean_heads_planes(const float* __restrict__ sc, float* __restrict__ out,
                                  __nv_bfloat16* __restrict__ ph, __nv_bfloat16* __restrict__ pl) {
    long long idx = (long long)blockIdx.x * 256 + threadIdx.x;
    const long long NN = (long long)B_ * C_ * C_;
    if (idx >= NN) return;
    long long b = idx / (C_ * C_);
    long long r = idx % (C_ * C_);
    float s = 0.f;
    #pragma unroll
    for (int h = 0; h < H_; h++)
        s += sc[(b * H_ + h) * (long long)(C_ * C_) + r];
    s *= 0.125f;
    out[idx] = s;
    __nv_bfloat16 h_, l_;
    split1(s, h_, l_);
    ph[idx] = h_;
    pl[idx] = l_;
}

// =================== cp.async + ldmatrix plane GEMM ========================
// All operands NT: A planes [M][K] (lda), B planes [N][K] (ldb), bf16 hi/lo.
#define FLAG_RELU    1
#define FLAG_TRISKIP 2
#define FLAG_KTRI    4
#define FLAG_SF32    8
#define FLAG_SPLANES 16
#define FLAG_SVT     32

template<int BN, int WN>
__global__ __launch_bounds__(128 * WN)
void mma_gemm(const __nv_bfloat16* __restrict__ Ah, const __nv_bfloat16* __restrict__ Al,
              int lda, long long sAo, long long sAi, int nInner,
              const __nv_bfloat16* __restrict__ Bh, const __nv_bfloat16* __restrict__ Bl,
              int ldb, long long sBo, long long sBi,
              float* __restrict__ Cf,
              __nv_bfloat16* __restrict__ Ph, __nv_bfloat16* __restrict__ Pl,
              int ldc, long long sCo, long long sCi,
              int K, float alpha, const float* __restrict__ bias,
              const float* __restrict__ res, int ldres, long long sRo, long long sRi,
              int flags) {
    constexpr int BM = 128, BK = 32;
    constexpr int THREADS = 128 * WN;
    constexpr int WNT = BN / WN;
    constexpr int NJ  = WNT / 8;
    constexpr int RS  = 40;                 // smem row stride (bf16 elems) = 80B
    constexpr int ASZ = BM * RS;
    constexpr int BSZ = BN * RS;
    constexpr int SSZ = 2 * ASZ + 2 * BSZ;  // elems per stage
    constexpr int STAGES = 3;
    constexpr int ACH = (BM * 4 * 2) / THREADS;
    constexpr int BCH = (BN * 4 * 2) / THREADS;

    if ((flags & FLAG_TRISKIP) && blockIdx.x > blockIdx.y) return;

    extern __shared__ __nv_bfloat16 sm[];
    unsigned smb = (unsigned)__cvta_generic_to_shared(sm);

    int z = blockIdx.z, zo = z / nInner, zi = z % nInner;
    const __nv_bfloat16* Abh = Ah + zo * sAo + zi * sAi;
    const __nv_bfloat16* Abl = Al + zo * sAo + zi * sAi;
    const __nv_bfloat16* Bbh = Bh + zo * sBo + zi * sBi;
    const __nv_bfloat16* Bbl = Bl + zo * sBo + zi * sBi;
    float* Cb = Cf ? Cf + zo * sCo + zi * sCi : (float*)0;
    __nv_bfloat16* Pbh = Ph ? Ph + zo * sCo + zi * sCi : (__nv_bfloat16*)0;
    __nv_bfloat16* Pbl = Pl ? Pl + zo * sCo + zi * sCi : (__nv_bfloat16*)0;
    const float* Rb = res ? (res + zo * sRo + zi * sRi) : (const float*)0;

    int tid = threadIdx.x, lane = tid & 31, wid = tid >> 5;
    int wm = wid & 3, wn = wid >> 2;
    int row0 = blockIdx.y * BM;
    int col0 = blockIdx.x * BN;
    int r = lane >> 2, cq = lane & 3;

    int Keff = (flags & FLAG_KTRI) ? min(K, row0 + BM) : K;
    int nk = Keff / BK;

    auto load_stage = [&](int s, int k0) {
        #pragma unroll
        for (int i = 0; i < ACH; i++) {
            int cid = tid + i * THREADS;
            int p = cid >> 9;            // 512 chunks per A plane
            int w = cid & 511;
            int m = w >> 2, kc = w & 3;
            const __nv_bfloat16* src = (p ? Abl : Abh)
                + (long long)(row0 + m) * lda + k0 + kc * 8;
            unsigned dst = smb + (unsigned)((s * SSZ + p * ASZ + m * RS + kc * 8) * 2);
            cpasync16(dst, src);
        }
        #pragma unroll
        for (int i = 0; i < BCH; i++) {
            int cid = tid + i * THREADS;
            int p = cid / (BN * 4);
            int w = cid % (BN * 4);
            int n = w >> 2, kc = w & 3;
            const __nv_bfloat16* src = (p ? Bbl : Bbh)
                + (long long)(col0 + n) * ldb + k0 + kc * 8;
            unsigned dst = smb + (unsigned)((s * SSZ + 2 * ASZ + p * BSZ + n * RS + kc * 8) * 2);
            cpasync16(dst, src);
        }
    };

    // per-thread ldmatrix row/chunk pieces
    int fRow = ((lane >> 3) & 1) * 8 + (lane & 7);
    int fCh  = lane >> 4;   // 0/1

    float acc[2][NJ][4];
    #pragma unroll
    for (int i = 0; i < 2; i++)
        #pragma unroll
        for (int j = 0; j < NJ; j++)
            #pragma unroll
            for (int e = 0; e < 4; e++) acc[i][j][e] = 0.f;

    auto compute = [&](int s) {
        #pragma unroll
        for (int k16 = 0; k16 < 2; k16++) {
            int ch = 2 * k16 + fCh;
            unsigned bfh[NJ][2], bfl[NJ][2];
            #pragma unroll
            for (int g = 0; g < NJ / 2; g++) {
                int nrow = wn * WNT + g * 16 + fRow;
                unsigned a0 = smb + (unsigned)((s * SSZ + 2 * ASZ + nrow * RS + ch * 8) * 2);
                unsigned r0, r1, r2, r3;
                ldm4(r0, r1, r2, r3, a0);
                bfh[2 * g][0] = r0; bfh[2 * g + 1][0] = r1;
                bfh[2 * g][1] = r2; bfh[2 * g + 1][1] = r3;
                ldm4(r0, r1, r2, r3, a0 + (unsigned)(BSZ * 2));
                bfl[2 * g][0] = r0; bfl[2 * g + 1][0] = r1;
                bfl[2 * g][1] = r2; bfl[2 * g + 1][1] = r3;
            }
            #pragma unroll
            for (int im = 0; im < 2; im++) {
                int mrow = wm * 32 + im * 16 + fRow;
                unsigned a0 = smb + (unsigned)((s * SSZ + mrow * RS + ch * 8) * 2);
                unsigned afh[4], afl[4];
                ldm4(afh[0], afh[1], afh[2], afh[3], a0);
                ldm4(afl[0], afl[1], afl[2], afl[3], a0 + (unsigned)(ASZ * 2));
                #pragma unroll
                for (int j = 0; j < NJ; j++) {
                    mma16(acc[im][j], afl, bfh[j]);
                    mma16(acc[im][j], afh, bfl[j]);
                    mma16(acc[im][j], afh, bfh[j]);
                }
            }
        }
    };

    // ---- pipelined mainloop ----
    #pragma unroll
    for (int s = 0; s < STAGES - 1; s++) {
        if (s < nk) { load_stage(s, s * BK); cp_commit(); }
    }
    for (int kb = 0; kb < nk; kb++) {
        if (kb + 2 <= nk) cp_wait<1>(); else cp_wait<0>();
        __syncthreads();
        compute(kb % STAGES);
        int kn = kb + STAGES - 1;
        if (kn < nk) { load_stage(kn % STAGES, kn * BK); cp_commit(); }
    }

    // ---- epilogue ----
    #pragma unroll
    for (int im = 0; im < 2; im++) {
        #pragma unroll
        for (int j = 0; j < NJ; j++) {
            int gm0 = row0 + wm * 32 + im * 16 + r;
            int gn  = col0 + wn * WNT + j * 8 + cq * 2;
            #pragma unroll
            for (int half = 0; half < 2; half++) {
                int gm = gm0 + half * 8;
                float v0 = acc[im][j][half * 2 + 0] * alpha;
                float v1 = acc[im][j][half * 2 + 1] * alpha;
                if (bias) { v0 += bias[gn]; v1 += bias[gn + 1]; }
                if (flags & FLAG_RELU) { v0 = fmaxf(v0, 0.f); v1 = fmaxf(v1, 0.f); }
                if (Rb) {
                    const float* rp = Rb + (long long)gm * ldres + gn;
                    v0 += rp[0]; v1 += rp[1];
                }
                if (flags & FLAG_SF32) {
                    float2 st; st.x = v0; st.y = v1;
                    *reinterpret_cast<float2*>(Cb + (long long)gm * ldc + gn) = st;
                }
                if (flags & FLAG_SPLANES) {
                    __nv_bfloat162 hi, lo;
                    split2v(v0, v1, hi, lo);
                    *reinterpret_cast<__nv_bfloat162*>(Pbh + (long long)gm * ldc + gn) = hi;
                    *reinterpret_cast<__nv_bfloat162*>(Pbl + (long long)gm * ldc + gn) = lo;
                }
                if (flags & FLAG_SVT) {
                    int bb = gm >> 9, t = gm & 511;
                    long long a0 = ((long long)bb * 256 + gn) * 512 + t;
                    __nv_bfloat16 h0, l0, h1, l1;
                    split1(v0, h0, l0);
                    split1(v1, h1, l1);
                    Ph[a0] = h0;       Pl[a0] = l0;
                    Ph[a0 + 512] = h1; Pl[a0 + 512] = l1;
                }
            }
        }
    }
}

#define SMEM_BYTES(BN) (3 * (2 * 128 * 40 + 2 * (BN) * 40) * 2)

static inline void gemmP(const __nv_bfloat16* Ah, const __nv_bfloat16* Al,
                         int lda, long long sAo, long long sAi,
                         const __nv_bfloat16* Bh, const __nv_bfloat16* Bl,
                         int ldb, long long sBo, long long sBi,
                         float* Cf, __nv_bfloat16* Ph, __nv_bfloat16* Pl,
                         int ldc, long long sCo, long long sCi,
                         int M, int N, int K, int bOuter, int bInner,
                         float alpha, const float* bias,
                         const float* res, int ldres, long long sRo, long long sRi,
                         int flags) {
    if (N == 32) {
        dim3 grid(1, M / 128, bOuter * bInner);
        mma_gemm<32, 1><<<grid, 128, SMEM_BYTES(32)>>>(
            Ah, Al, lda, sAo, sAi, bInner, Bh, Bl, ldb, sBo, sBi,
            Cf, Ph, Pl, ldc, sCo, sCi, K, alpha, bias, res, ldres, sRo, sRi, flags);
    } else {
        dim3 grid(N / 128, M / 128, bOuter * bInner);
        mma_gemm<128, 2><<<grid, 256, SMEM_BYTES(128)>>>(
            Ah, Al, lda, sAo, sAi, bInner, Bh, Bl, ldb, sBo, sBi,
            Cf, Ph, Pl, ldc, sCo, sCi, K, alpha, bias, res, ldres, sRo, sRi, flags);
    }
}

// ================================ Launch ===================================
extern "C" void kernel_launch(void* const* d_in, const int* in_sizes, int n_in,
                              void* d_out, int out_size) {
    static int cfg = 0;
    if (!cfg) {
        cudaFuncSetAttribute((const void*)mma_gemm<128, 2>,
                             cudaFuncAttributeMaxDynamicSharedMemorySize, SMEM_BYTES(128));
        cudaFuncSetAttribute((const void*)mma_gemm<32, 1>,
                             cudaFuncAttributeMaxDynamicSharedMemorySize, SMEM_BYTES(32));
        cfg = 1;
    }

    const float* x_T     = (const float*)d_in[0];
    const float* x_S     = (const float*)d_in[1];
    const float* Wq_t    = (const float*)d_in[2];
    const float* Wk_t    = (const float*)d_in[3];
    const float* Wv_t    = (const float*)d_in[4];
    const float* Wo      = (const float*)d_in[5];
    const float* Wq_s    = (const float*)d_in[6];
    const float* Wk_s    = (const float*)d_in[7];
    const float* ff1_w1  = (const float*)d_in[8];
    const float* ff1_b1  = (const float*)d_in[9];
    const float* ff1_w2  = (const float*)d_in[10];
    const float* ff1_b2  = (const float*)d_in[11];
    const float* ff2_w1  = (const float*)d_in[12];
    const float* ff2_b1  = (const float*)d_in[13];
    const float* ff2_w2  = (const float*)d_in[14];
    const float* ff2_b2  = (const float*)d_in[15];
    const float* t_ln1_w = (const float*)d_in[16];
    const float* t_ln1_b = (const float*)d_in[17];
    const float* t_ln2_w = (const float*)d_in[18];
    const float* t_ln2_b = (const float*)d_in[19];
    const float* s_ln1_w = (const float*)d_in[20];
    const float* s_ln1_b = (const float*)d_in[21];
    const float* fus_ln_w= (const float*)d_in[22];
    const float* fus_ln_b= (const float*)d_in[23];

    float* out = (float*)d_out;             // [B,T,C]
    float* sw  = out + (size_t)N_BTC;       // [B,C,C]

    float* gf = 0;
    cudaGetSymbolAddress((void**)&gf, g_f);
    __nv_bfloat16* gp = 0;
    cudaGetSymbolAddress((void**)&gp, g_p);

    float* scT  = gf + FF_scT;
    float* scS  = gf + FF_scS;
    float* xb   = gf + FF_xb;
    float* x2b  = gf + FF_x2b;
    float* tout = gf + FF_tout;

    #define PH(name) (gp + PP_##name)
    #define PL2(name, sz) (gp + PP_##name + (long long)(sz))

    __nv_bfloat16 *h_h = PH(h),    *h_l = PL2(h, N_BTC);
    __nv_bfloat16 *q_h = PH(q),    *q_l = PL2(q, N_BTC);
    __nv_bfloat16 *k_h = PH(k),    *k_l = PL2(k, N_BTC);
    __nv_bfloat16 *vT_h = PH(vT),  *vT_l = PL2(vT, N_BTC);
    __nv_bfloat16 *at_h = PH(att), *at_l = PL2(att, N_SCT);
    __nv_bfloat16 *ob_h = PH(ob),  *ob_l = PL2(ob, N_BTC);
    __nv_bfloat16 *h2_h = PH(h2),  *h2_l = PL2(h2, N_BTC);
    __nv_bfloat16 *ff_h = PH(ffb), *ff_l = PL2(ffb, N_FF);
    __nv_bfloat16 *to_h = PH(tout),*to_l = PL2(tout, N_BTC);
    __nv_bfloat16 *hs_h = PH(hs),  *hs_l = PL2(hs, N_BTC);
    __nv_bfloat16 *qs_h = PH(qs),  *qs_l = PL2(qs, N_BTC);
    __nv_bfloat16 *ks_h = PH(ks),  *ks_l = PL2(ks, N_BTC);
    __nv_bfloat16 *h3_h = PH(h3),  *h3_l = PL2(h3, N_BTC);
    __nv_bfloat16 *sw_h = PH(sw),  *sw_l = PL2(sw, N_CC);
    __nv_bfloat16 *wqt_h = PH(wqt), *wqt_l = PL2(wqt, 65536);
    __nv_bfloat16 *wkt_h = PH(wkt), *wkt_l = PL2(wkt, 65536);
    __nv_bfloat16 *wvt_h = PH(wvt), *wvt_l = PL2(wvt, 65536);
    __nv_bfloat16 *wo_h  = PH(wo),  *wo_l  = PL2(wo, 65536);
    __nv_bfloat16 *wqs_h = PH(wqs), *wqs_l = PL2(wqs, 262144);
    __nv_bfloat16 *wks_h = PH(wks), *wks_l = PL2(wks, 262144);
    __nv_bfloat16 *f1w1_h = PH(f1w1), *f1w1_l = PL2(f1w1, 262144);
    __nv_bfloat16 *f1w2_h = PH(f1w2), *f1w2_l = PL2(f1w2, 262144);
    __nv_bfloat16 *f2w1_h = PH(f2w1), *f2w1_l = PL2(f2w1, 262144);
    __nv_bfloat16 *f2w2_h = PH(f2w2), *f2w2_l = PL2(f2w2, 262144);

    const long long TC = (long long)T_ * C_;
    const long long TT = (long long)T_ * T_;
    const long long CC = (long long)C_ * C_;

    // ---- weight splits ----
    split_kernel<<<64, 256>>>(Wq_t, wqt_h, wqt_l, 65536 / 4);
    split_kernel<<<64, 256>>>(Wk_t, wkt_h, wkt_l, 65536 / 4);
    split_kernel<<<64, 256>>>(Wv_t, wvt_h, wvt_l, 65536 / 4);
    split_kernel<<<64, 256>>>(Wo,   wo_h,  wo_l,  65536 / 4);
    split_kernel<<<256, 256>>>(Wq_s, wqs_h, wqs_l, 262144 / 4);
    split_kernel<<<256, 256>>>(Wk_s, wks_h, wks_l, 262144 / 4);
    split_kernel<<<256, 256>>>(ff1_w1, f1w1_h, f1w1_l, 262144 / 4);
    split_kernel<<<256, 256>>>(ff1_w2, f1w2_h, f1w2_l, 262144 / 4);
    split_kernel<<<256, 256>>>(ff2_w1, f2w1_h, f2w1_l, 262144 / 4);
    split_kernel<<<256, 256>>>(ff2_w2, f2w2_h, f2w2_l, 262144 / 4);

    // ---- temporal branch ----
    ln_planes_kernel<<<B_ * T_, 256>>>(x_T, h_h, h_l, t_ln1_w, t_ln1_b, C_);

    gemmP(h_h, h_l, C_, 0, 0, wqt_h, wqt_l, C_, 0, 0,
          0, q_h, q_l, C_, 0, 0, B_*T_, C_, C_, 1, 1,
          1.f, 0, 0, 0, 0, 0, FLAG_SPLANES);
    gemmP(h_h, h_l, C_, 0, 0, wkt_h, wkt_l, C_, 0, 0,
          0, k_h, k_l, C_, 0, 0, B_*T_, C_, C_, 1, 1,
          1.f, 0, 0, 0, 0, 0, FLAG_SPLANES);
    gemmP(h_h, h_l, C_, 0, 0, wvt_h, wvt_l, C_, 0, 0,
          0, vT_h, vT_l, C_, 0, 0, B_*T_, C_, C_, 1, 1,
          1.f, 0, 0, 0, 0, 0, FLAG_SVT);

    // scores[b,h,t,s] = q.k / sqrt(32)  (TRISKIP)
    gemmP(q_h, q_l, C_, TC, HST, k_h, k_l, C_, TC, HST,
          scT, 0, 0, T_, (long long)H_*TT, TT,
          T_, T_, HST, B_, H_,
          0.1767766952966369f, 0, 0, 0, 0, 0, FLAG_TRISKIP | FLAG_SF32);

    softmax_causal_planes<<<B_ * H_ * T_, 256>>>(scT, at_h, at_l);

    // o = att @ v  (N=32, KTRI) -> ob planes
    gemmP(at_h, at_l, T_, (long long)H_*TT, TT,
          vT_h, vT_l, T_, (long long)C_*T_, 32LL*T_,
          0, ob_h, ob_l, C_, TC, HST,
          T_, HST, T_, B_, H_,
          1.f, 0, 0, 0, 0, 0, FLAG_KTRI | FLAG_SPLANES);

    // x = x_T + o @ Wo^T
    gemmP(ob_h, ob_l, C_, 0, 0, wo_h, wo_l, C_, 0, 0,
          xb, 0, 0, C_, 0, 0, B_*T_, C_, C_, 1, 1,
          1.f, 0, x_T, C_, 0, 0, FLAG_SF32);

    ln_planes_kernel<<<B_ * T_, 256>>>(xb, h2_h, h2_l, t_ln2_w, t_ln2_b, C_);

    gemmP(h2_h, h2_l, C_, 0, 0, f1w1_h, f1w1_l, C_, 0, 0,
          0, ff_h, ff_l, 4*C_, 0, 0, B_*T_, 4*C_, C_, 1, 1,
          1.f, ff1_b1, 0, 0, 0, 0, FLAG_RELU | FLAG_SPLANES);
    gemmP(ff_h, ff_l, 4*C_, 0, 0, f1w2_h, f1w2_l, 4*C_, 0, 0,
          tout, to_h, to_l, C_, 0, 0, B_*T_, C_, 4*C_, 1, 1,
          1.f, ff1_b2, xb, C_, 0, 0, FLAG_SF32 | FLAG_SPLANES);

    // ---- spatial branch ----
    ln_planes_kernel<<<B_ * C_, 256>>>(x_S, hs_h, hs_l, s_ln1_w, s_ln1_b, T_);

    gemmP(hs_h, hs_l, T_, 0, 0, wqs_h, wqs_l, T_, 0, 0,
          0, qs_h, qs_l, T_, 0, 0, B_*C_, T_, T_, 1, 1,
          1.f, 0, 0, 0, 0, 0, FLAG_SPLANES);
    gemmP(hs_h, hs_l, T_, 0, 0, wks_h, wks_l, T_, 0, 0,
          0, ks_h, ks_l, T_, 0, 0, B_*C_, T_, T_, 1, 1,
          1.f, 0, 0, 0, 0, 0, FLAG_SPLANES);

    gemmP(qs_h, qs_l, T_, (long long)C_*T_, HSS, ks_h, ks_l, T_, (long long)C_*T_, HSS,
          scS, 0, 0, C_, (long long)H_*CC, CC,
          C_, C_, HSS, B_, H_,
          0.125f, 0, 0, 0, 0, 0, FLAG_SF32);

    softmax_kernel<<<B_ * H_ * C_, 256>>>(scS, C_);
    mean_heads_planes<<<(B_*C_*C_ + 255) / 256, 256>>>(scS, sw, sw_h, sw_l);

    // ---- fusion ----
    gemmP(to_h, to_l, C_, TC, 0, sw_h, sw_l, C_, CC, 0,
          x2b, 0, 0, C_, TC, 0,
          T_, C_, C_, B_, 1,
          1.f, 0, tout, C_, TC, 0, FLAG_SF32);

    ln_planes_kernel<<<B_ * T_, 256>>>(x2b, h3_h, h3_l, fus_ln_w, fus_ln_b, C_);

    gemmP(h3_h, h3_l, C_, 0, 0, f2w1_h, f2w1_l, C_, 0, 0,
          0, ff_h, ff_l, 4*C_, 0, 0, B_*T_, 4*C_, C_, 1, 1,
          1.f, ff2_b1, 0, 0, 0, 0, FLAG_RELU | FLAG_SPLANES);
    gemmP(ff_h, ff_l, 4*C_, 0, 0, f2w2_h, f2w2_l, 4*C_, 0, 0,
          out, 0, 0, C_, 0, 0, B_*T_, C_, 4*C_, 1, 1,
          1.f, ff2_b2, x2b, C_, 0, 0, FLAG_SF32);
}

// round 8
// speedup vs baseline: 1.0664x; 1.0664x over previous
#include <cuda_runtime.h>
#include <cuda_bf16.h>
#include <math.h>

#define B_  16
#define T_  512
#define C_  256
#define H_  8
#define HST 32
#define HSS 64

#define N_BTC (B_*T_*C_)
#define N_FF  (B_*T_*4*C_)
#define N_SCT ((long long)B_*H_*T_*T_)
#define N_SCS ((long long)B_*H_*C_*C_)

#define O_h    0
#define O_q    (O_h    + N_BTC)
#define O_k    (O_q    + N_BTC)
#define O_v    (O_k    + N_BTC)
#define O_o    (O_v    + N_BTC)
#define O_x    (O_o    + N_BTC)
#define O_h2   (O_x    + N_BTC)
#define O_tout (O_h2   + N_BTC)
#define O_hs   (O_tout + N_BTC)
#define O_qs   (O_hs   + N_BTC)
#define O_ks   (O_qs   + N_BTC)
#define O_x2   (O_ks   + N_BTC)
#define O_h3   (O_x2   + N_BTC)
#define O_ff   (O_h3   + N_BTC)
#define O_scT  (O_ff   + N_FF)
#define O_scS  (O_scT  + N_SCT)
#define TOTAL_SCRATCH (O_scS + N_SCS)

__device__ float g_buf[TOTAL_SCRATCH];

// ============================== LayerNorm ==================================
__global__ void ln_kernel(const float* __restrict__ x, float* __restrict__ y,
                          const float* __restrict__ w, const float* __restrict__ b,
                          int L) {
    long long base = (long long)blockIdx.x * L;
    int tid = threadIdx.x;
    float s = 0.f, s2 = 0.f;
    for (int i = tid; i < L; i += 256) {
        float v = x[base + i];
        s += v; s2 += v * v;
    }
    __shared__ float sh[64];
    #pragma unroll
    for (int o = 16; o > 0; o >>= 1) {
        s  += __shfl_down_sync(0xffffffffu, s,  o);
        s2 += __shfl_down_sync(0xffffffffu, s2, o);
    }
    int warp = tid >> 5, lane = tid & 31;
    if (lane == 0) { sh[warp] = s; sh[warp + 32] = s2; }
    __syncthreads();
    if (tid == 0) {
        float ts = 0.f, ts2 = 0.f;
        for (int i = 0; i < 8; i++) { ts += sh[i]; ts2 += sh[32 + i]; }
        float m = ts / (float)L;
        float var = ts2 / (float)L - m * m;
        sh[0] = m;
        sh[1] = rsqrtf(var + 1e-6f);
    }
    __syncthreads();
    float m = sh[0], r = sh[1];
    for (int i = tid; i < L; i += 256)
        y[base + i] = (x[base + i] - m) * r * w[i] + b[i];
}

// ===================== Softmax (full row, length L<=512) ===================
__global__ void softmax_kernel(float* __restrict__ x, int L) {
    long long base = (long long)blockIdx.x * L;
    int tid = threadIdx.x;
    float v[2];
    #pragma unroll
    for (int c = 0; c < 2; c++) {
        int i = tid + c * 256;
        v[c] = (i < L) ? x[base + i] : -3.4e38f;
    }
    float mx = fmaxf(v[0], v[1]);
    __shared__ float sh[32];
    #pragma unroll
    for (int o = 16; o > 0; o >>= 1) mx = fmaxf(mx, __shfl_down_sync(0xffffffffu, mx, o));
    int warp = tid >> 5, lane = tid & 31;
    if (lane == 0) sh[warp] = mx;
    __syncthreads();
    if (tid == 0) {
        float m = sh[0];
        for (int i = 1; i < 8; i++) m = fmaxf(m, sh[i]);
        sh[0] = m;
    }
    __syncthreads();
    mx = sh[0];
    float sum = 0.f;
    #pragma unroll
    for (int c = 0; c < 2; c++) {
        int i = tid + c * 256;
        if (i < L) { v[c] = expf(v[c] - mx); sum += v[c]; }
    }
    __syncthreads();
    #pragma unroll
    for (int o = 16; o > 0; o >>= 1) sum += __shfl_down_sync(0xffffffffu, sum, o);
    if (lane == 0) sh[warp] = sum;
    __syncthreads();
    if (tid == 0) {
        float s = 0.f;
        for (int i = 0; i < 8; i++) s += sh[i];
        sh[0] = 1.f / s;
    }
    __syncthreads();
    float inv = sh[0];
    #pragma unroll
    for (int c = 0; c < 2; c++) {
        int i = tid + c * 256;
        if (i < L) x[base + i] = v[c] * inv;
    }
}

// ============== Causal softmax over rows of length T_ (=512) ===============
__global__ void softmax_causal_kernel(float* __restrict__ x) {
    long long base = (long long)blockIdx.x * T_;
    int t = blockIdx.x % T_;
    int tid = threadIdx.x;
    float v[2];
    bool act[2];
    #pragma unroll
    for (int c = 0; c < 2; c++) {
        int i = tid + c * 256;
        act[c] = (i <= t);
        v[c] = act[c] ? x[base + i] : -3.4e38f;
    }
    float mx = fmaxf(v[0], v[1]);
    __shared__ float sh[32];
    #pragma unroll
    for (int o = 16; o > 0; o >>= 1) mx = fmaxf(mx, __shfl_down_sync(0xffffffffu, mx, o));
    int warp = tid >> 5, lane = tid & 31;
    if (lane == 0) sh[warp] = mx;
    __syncthreads();
    if (tid == 0) {
        float m = sh[0];
        for (int i = 1; i < 8; i++) m = fmaxf(m, sh[i]);
        sh[0] = m;
    }
    __syncthreads();
    mx = sh[0];
    float sum = 0.f;
    #pragma unroll
    for (int c = 0; c < 2; c++) {
        if (act[c]) { v[c] = expf(v[c] - mx); sum += v[c]; }
    }
    __syncthreads();
    #pragma unroll
    for (int o = 16; o > 0; o >>= 1) sum += __shfl_down_sync(0xffffffffu, sum, o);
    if (lane == 0) sh[warp] = sum;
    __syncthreads();
    if (tid == 0) {
        float s = 0.f;
        for (int i = 0; i < 8; i++) s += sh[i];
        sh[0] = 1.f / s;
    }
    __syncthreads();
    float inv = sh[0];
    #pragma unroll
    for (int c = 0; c < 2; c++) {
        int i = tid + c * 256;
        x[base + i] = act[c] ? v[c] * inv : 0.f;
    }
}

// ============================ Mean over heads ==============================
__global__ void mean_heads_kernel(const float* __restrict__ sc, float* __restrict__ out) {
    long long idx = (long long)blockIdx.x * 256 + threadIdx.x;
    const long long NN = (long long)B_ * C_ * C_;
    if (idx >= NN) return;
    long long b = idx / (C_ * C_);
    long long r = idx % (C_ * C_);
    float s = 0.f;
    #pragma unroll
    for (int h = 0; h < H_; h++)
        s += sc[(b * H_ + h) * (long long)(C_ * C_) + r];
    out[idx] = s * 0.125f;
}

// ========== Pipelined tensor-core GEMM (3x BF16) with ldmatrix =============
#define FLAG_RELU    1
#define FLAG_NT      4
#define FLAG_TRISKIP 8
#define FLAG_KTRI    16

__device__ __forceinline__ void split2v(float x0, float x1, __nv_bfloat162 &hi, __nv_bfloat162 &lo) {
    hi = __floats2bfloat162_rn(x0, x1);
    lo = __floats2bfloat162_rn(x0 - __bfloat162float(hi.x), x1 - __bfloat162float(hi.y));
}
__device__ __forceinline__ void split1(float x, __nv_bfloat16 &h, __nv_bfloat16 &l) {
    h = __float2bfloat16_rn(x);
    l = __float2bfloat16_rn(x - __bfloat162float(h));
}
__device__ __forceinline__ void ldm4(unsigned &r0, unsigned &r1, unsigned &r2, unsigned &r3, unsigned a) {
    asm volatile("ldmatrix.sync.aligned.m8n8.x4.shared.b16 {%0,%1,%2,%3}, [%4];"
        : "=r"(r0), "=r"(r1), "=r"(r2), "=r"(r3) : "r"(a));
}
__device__ __forceinline__ void mma16(float* c, const unsigned* a, const unsigned* b) {
    asm volatile("mma.sync.aligned.m16n8k16.row.col.f32.bf16.bf16.f32 "
        "{%0,%1,%2,%3}, {%4,%5,%6,%7}, {%8,%9}, {%0,%1,%2,%3};"
        : "+f"(c[0]), "+f"(c[1]), "+f"(c[2]), "+f"(c[3])
        : "r"(a[0]), "r"(a[1]), "r"(a[2]), "r"(a[3]), "r"(b[0]), "r"(b[1]));
}

template<int BN, int WN>
__global__ __launch_bounds__(128 * WN)
void mma_gemm(const float* __restrict__ A, int lda, long long sAo, long long sAi, int nInner,
              const float* __restrict__ Bm, int ldb, long long sBo, long long sBi,
              float* __restrict__ Cm, int ldc, long long sCo, long long sCi,
              int K, float alpha,
              const float* __restrict__ bias,
              const float* __restrict__ res, int ldres, long long sRo, long long sRi,
              int flags) {
    constexpr int BM = 128, BK = 32;
    constexpr int THREADS = 128 * WN;
    constexpr int WNT = BN / WN;
    constexpr int NJ  = WNT / 8;
    constexpr int RS  = 40;                  // smem row stride (bf16) = 80 B
    constexpr int ASZ = BM * RS;
    constexpr int BSZ = BN * RS;
    constexpr int SSZ = 2 * (ASZ + BSZ);     // elems per buffer (hi+lo, A+B)
    constexpr int AITER = (BM * 8) / THREADS;
    constexpr int BITER = (BN * 8) / THREADS;

    if ((flags & FLAG_TRISKIP) && blockIdx.x > blockIdx.y) return;

    extern __shared__ __nv_bfloat16 sm[];
    unsigned smb = (unsigned)__cvta_generic_to_shared(sm);

    int z  = blockIdx.z;
    int zo = z / nInner, zi = z % nInner;
    const float* Ab = A  + zo * sAo + zi * sAi;
    const float* Bb = Bm + zo * sBo + zi * sBi;
    float*       Cb = Cm + zo * sCo + zi * sCi;
    const float* Rb = res ? (res + zo * sRo + zi * sRi) : (const float*)0;

    int tid = threadIdx.x, lane = tid & 31, wid = tid >> 5;
    int wm = wid & 3, wn = wid >> 2;
    int row0 = blockIdx.y * BM;
    int col0 = blockIdx.x * BN;
    int r = lane >> 2, cq = lane & 3;
    bool nt = (flags & FLAG_NT) != 0;

    int Keff = (flags & FLAG_KTRI) ? min(K, row0 + BM) : K;
    int nk = Keff / BK;

    float4 ra[AITER], rb[BITER];

    auto loadT = [&](int k0) {
        #pragma unroll
        for (int i = 0; i < AITER; i++) {
            int idx = tid + i * THREADS;
            int m = idx >> 3, k4 = idx & 7;
            ra[i] = *reinterpret_cast<const float4*>(
                Ab + (long long)(row0 + m) * lda + k0 + k4 * 4);
        }
        if (nt) {
            #pragma unroll
            for (int i = 0; i < BITER; i++) {
                int idx = tid + i * THREADS;
                int n = idx >> 3, k4 = idx & 7;
                rb[i] = *reinterpret_cast<const float4*>(
                    Bb + (long long)(col0 + n) * ldb + k0 + k4 * 4);
            }
        } else {
            #pragma unroll
            for (int i = 0; i < BITER; i++) {
                #pragma unroll
                for (int pz = 0; pz < 2; pz++) {
                    int pidx = tid + (i * 2 + pz) * THREADS;
                    int kk2 = pidx / BN;
                    int n = pidx % BN;
                    const float* bp = Bb + (long long)(k0 + kk2 * 2) * ldb + col0 + n;
                    float b0 = bp[0], b1 = bp[ldb];
                    if (pz == 0) { rb[i].x = b0; rb[i].y = b1; }
                    else         { rb[i].z = b0; rb[i].w = b1; }
                }
            }
        }
    };

    auto storeT = [&](int s) {
        __nv_bfloat16* ah = sm + s * SSZ;
        __nv_bfloat16* al = ah + ASZ;
        __nv_bfloat16* bh = ah + 2 * ASZ;
        __nv_bfloat16* bl = bh + BSZ;
        #pragma unroll
        for (int i = 0; i < AITER; i++) {
            int idx = tid + i * THREADS;
            int m = idx >> 3, k4 = idx & 7;
            __nv_bfloat162 h0, l0, h1, l1;
            split2v(ra[i].x, ra[i].y, h0, l0);
            split2v(ra[i].z, ra[i].w, h1, l1);
            *reinterpret_cast<__nv_bfloat162*>(ah + m * RS + k4 * 4)     = h0;
            *reinterpret_cast<__nv_bfloat162*>(ah + m * RS + k4 * 4 + 2) = h1;
            *reinterpret_cast<__nv_bfloat162*>(al + m * RS + k4 * 4)     = l0;
            *reinterpret_cast<__nv_bfloat162*>(al + m * RS + k4 * 4 + 2) = l1;
        }
        if (nt) {
            #pragma unroll
            for (int i = 0; i < BITER; i++) {
                int idx = tid + i * THREADS;
                int n = idx >> 3, k4 = idx & 7;
                __nv_bfloat162 h0, l0, h1, l1;
                split2v(rb[i].x, rb[i].y, h0, l0);
                split2v(rb[i].z, rb[i].w, h1, l1);
                *reinterpret_cast<__nv_bfloat162*>(bh + n * RS + k4 * 4)     = h0;
                *reinterpret_cast<__nv_bfloat162*>(bh + n * RS + k4 * 4 + 2) = h1;
                *reinterpret_cast<__nv_bfloat162*>(bl + n * RS + k4 * 4)     = l0;
                *reinterpret_cast<__nv_bfloat162*>(bl + n * RS + k4 * 4 + 2) = l1;
            }
        } else {
            // rb holds B[k][n]: pairs (k=2kk2, 2kk2+1) for column n -> store at [n][k]
            #pragma unroll
            for (int i = 0; i < BITER; i++) {
                #pragma unroll
                for (int pz = 0; pz < 2; pz++) {
                    int pidx = tid + (i * 2 + pz) * THREADS;
                    int kk2 = pidx / BN;
                    int n = pidx % BN;
                    float b0 = pz ? rb[i].z : rb[i].x;
                    float b1 = pz ? rb[i].w : rb[i].y;
                    __nv_bfloat162 h0, l0;
                    split2v(b0, b1, h0, l0);
                    *reinterpret_cast<__nv_bfloat162*>(bh + n * RS + kk2 * 2) = h0;
                    *reinterpret_cast<__nv_bfloat162*>(bl + n * RS + kk2 * 2) = l0;
                }
            }
        }
    };

    float acc[2][NJ][4];
    #pragma unroll
    for (int i = 0; i < 2; i++)
        #pragma unroll
        for (int j = 0; j < NJ; j++)
            #pragma unroll
            for (int e = 0; e < 4; e++) acc[i][j][e] = 0.f;

    // ldmatrix per-lane row/chunk
    int fRow = ((lane >> 3) & 1) * 8 + (lane & 7);
    int fCh  = lane >> 4;   // 0/1

    auto compute = [&](int s) {
        unsigned ahB = smb + (unsigned)((s * SSZ) * 2);
        unsigned alB = ahB + (unsigned)(ASZ * 2);
        unsigned bhB = ahB + (unsigned)(2 * ASZ * 2);
        unsigned blB = bhB + (unsigned)(BSZ * 2);
        #pragma unroll
        for (int k16 = 0; k16 < 2; k16++) {
            int ch = 2 * k16 + fCh;                   // 8-elem k chunk per lane
            unsigned bfh[NJ][2], bfl[NJ][2];
            #pragma unroll
            for (int g = 0; g < NJ / 2; g++) {
                int nrow = wn * WNT + g * 16 + fRow;
                unsigned a0 = bhB + (unsigned)((nrow * RS + ch * 8) * 2);
                unsigned r0, r1, r2, r3;
                ldm4(r0, r1, r2, r3, a0);
                bfh[2 * g][0] = r0; bfh[2 * g + 1][0] = r1;
                bfh[2 * g][1] = r2; bfh[2 * g + 1][1] = r3;
                unsigned a1 = blB + (unsigned)((nrow * RS + ch * 8) * 2);
                ldm4(r0, r1, r2, r3, a1);
                bfl[2 * g][0] = r0; bfl[2 * g + 1][0] = r1;
                bfl[2 * g][1] = r2; bfl[2 * g + 1][1] = r3;
            }
            #pragma unroll
            for (int im = 0; im < 2; im++) {
                int mrow = wm * 32 + im * 16 + fRow;
                unsigned afh[4], afl[4];
                ldm4(afh[0], afh[1], afh[2], afh[3],
                     ahB + (unsigned)((mrow * RS + ch * 8) * 2));
                ldm4(afl[0], afl[1], afl[2], afl[3],
                     alB + (unsigned)((mrow * RS + ch * 8) * 2));
                #pragma unroll
                for (int j = 0; j < NJ; j++) {
                    mma16(acc[im][j], afl, bfh[j]);
                    mma16(acc[im][j], afh, bfl[j]);
                    mma16(acc[im][j], afh, bfh[j]);
                }
            }
        }
    };

    // ---- pipelined mainloop: 1 sync per iteration, double-buffered ----
    loadT(0);
    storeT(0);
    int p = 0;
    for (int kb = 0; kb < nk; kb++) {
        __syncthreads();
        bool more = (kb + 1) < nk;
        if (more) loadT((kb + 1) * BK);
        compute(p);
        if (more) storeT(1 - p);
        p ^= 1;
    }

    // ---- epilogue ----
    #pragma unroll
    for (int im = 0; im < 2; im++) {
        #pragma unroll
        for (int j = 0; j < NJ; j++) {
            int gm0 = row0 + wm * 32 + im * 16 + r;
            int gn  = col0 + wn * WNT + j * 8 + cq * 2;
            #pragma unroll
            for (int half = 0; half < 2; half++) {
                int gm = gm0 + half * 8;
                float v0 = acc[im][j][half * 2 + 0] * alpha;
                float v1 = acc[im][j][half * 2 + 1] * alpha;
                if (bias) { v0 += bias[gn]; v1 += bias[gn + 1]; }
                if (flags & FLAG_RELU) { v0 = fmaxf(v0, 0.f); v1 = fmaxf(v1, 0.f); }
                if (Rb) {
                    const float* rp = Rb + (long long)gm * ldres + gn;
                    v0 += rp[0]; v1 += rp[1];
                }
                float2 st; st.x = v0; st.y = v1;
                *reinterpret_cast<float2*>(Cb + (long long)gm * ldc + gn) = st;
            }
        }
    }
}

#define SMEM_BYTES(BN) (320 * (128 + (BN)))

static inline void gemm(const float* A, int lda, long long sAo, long long sAi,
                        const float* Bm, int ldb, long long sBo, long long sBi,
                        float* Cm, int ldc, long long sCo, long long sCi,
                        int M, int N, int K, int bOuter, int bInner,
                        float alpha, const float* bias,
                        const float* res, int ldres, long long sRo, long long sRi,
                        int flags) {
    if (N == 32) {
        dim3 grid(1, M / 128, bOuter * bInner);
        mma_gemm<32, 1><<<grid, 128, SMEM_BYTES(32)>>>(
            A, lda, sAo, sAi, bInner, Bm, ldb, sBo, sBi, Cm, ldc, sCo, sCi,
            K, alpha, bias, res, ldres, sRo, sRi, flags);
    } else {
        dim3 grid(N / 128, M / 128, bOuter * bInner);
        mma_gemm<128, 2><<<grid, 256, SMEM_BYTES(128)>>>(
            A, lda, sAo, sAi, bInner, Bm, ldb, sBo, sBi, Cm, ldc, sCo, sCi,
            K, alpha, bias, res, ldres, sRo, sRi, flags);
    }
}

// ================================ Launch ===================================
extern "C" void kernel_launch(void* const* d_in, const int* in_sizes, int n_in,
                              void* d_out, int out_size) {
    static int smem_cfg = 0;
    if (!smem_cfg) {
        cudaFuncSetAttribute((const void*)mma_gemm<128, 2>,
                             cudaFuncAttributeMaxDynamicSharedMemorySize, SMEM_BYTES(128));
        cudaFuncSetAttribute((const void*)mma_gemm<32, 1>,
                             cudaFuncAttributeMaxDynamicSharedMemorySize, SMEM_BYTES(32));
        smem_cfg = 1;
    }

    const float* x_T     = (const float*)d_in[0];
    const float* x_S     = (const float*)d_in[1];
    const float* Wq_t    = (const float*)d_in[2];
    const float* Wk_t    = (const float*)d_in[3];
    const float* Wv_t    = (const float*)d_in[4];
    const float* Wo      = (const float*)d_in[5];
    const float* Wq_s    = (const float*)d_in[6];
    const float* Wk_s    = (const float*)d_in[7];
    const float* ff1_w1  = (const float*)d_in[8];
    const float* ff1_b1  = (const float*)d_in[9];
    const float* ff1_w2  = (const float*)d_in[10];
    const float* ff1_b2  = (const float*)d_in[11];
    const float* ff2_w1  = (const float*)d_in[12];
    const float* ff2_b1  = (const float*)d_in[13];
    const float* ff2_w2  = (const float*)d_in[14];
    const float* ff2_b2  = (const float*)d_in[15];
    const float* t_ln1_w = (const float*)d_in[16];
    const float* t_ln1_b = (const float*)d_in[17];
    const float* t_ln2_w = (const float*)d_in[18];
    const float* t_ln2_b = (const float*)d_in[19];
    const float* s_ln1_w = (const float*)d_in[20];
    const float* s_ln1_b = (const float*)d_in[21];
    const float* fus_ln_w= (const float*)d_in[22];
    const float* fus_ln_b= (const float*)d_in[23];

    float* out = (float*)d_out;                 // [B,T,C]
    float* sw  = out + (size_t)N_BTC;           // [B,C,C]

    float* g = 0;
    cudaGetSymbolAddress((void**)&g, g_buf);
    float* h    = g + O_h;
    float* q    = g + O_q;
    float* k    = g + O_k;
    float* v    = g + O_v;
    float* ob   = g + O_o;
    float* xb   = g + O_x;
    float* h2   = g + O_h2;
    float* tout = g + O_tout;
    float* hs   = g + O_hs;
    float* qs   = g + O_qs;
    float* ks   = g + O_ks;
    float* x2b  = g + O_x2;
    float* h3   = g + O_h3;
    float* ffb  = g + O_ff;
    float* scT  = g + O_scT;
    float* scS  = g + O_scS;

    const long long TC = (long long)T_ * C_;
    const long long TT = (long long)T_ * T_;
    const long long CC = (long long)C_ * C_;

    // ---- temporal branch ----
    ln_kernel<<<B_ * T_, 256>>>(x_T, h, t_ln1_w, t_ln1_b, C_);

    gemm(h, C_, 0, 0, Wq_t, C_, 0, 0, q, C_, 0, 0, B_*T_, C_, C_, 1, 1,
         1.f, 0, 0, 0, 0, 0, FLAG_NT);
    gemm(h, C_, 0, 0, Wk_t, C_, 0, 0, k, C_, 0, 0, B_*T_, C_, C_, 1, 1,
         1.f, 0, 0, 0, 0, 0, FLAG_NT);
    gemm(h, C_, 0, 0, Wv_t, C_, 0, 0, v, C_, 0, 0, B_*T_, C_, C_, 1, 1,
         1.f, 0, 0, 0, 0, 0, FLAG_NT);

    gemm(q, C_, TC, HST, k, C_, TC, HST,
         scT, T_, (long long)H_*TT, TT,
         T_, T_, HST, B_, H_,
         0.1767766952966369f, 0, 0, 0, 0, 0, FLAG_NT | FLAG_TRISKIP);

    softmax_causal_kernel<<<B_ * H_ * T_, 256>>>(scT);

    gemm(scT, T_, (long long)H_*TT, TT, v, C_, TC, HST,
         ob, C_, TC, HST,
         T_, HST, T_, B_, H_,
         1.f, 0, 0, 0, 0, 0, FLAG_KTRI);

    gemm(ob, C_, 0, 0, Wo, C_, 0, 0, xb, C_, 0, 0, B_*T_, C_, C_, 1, 1,
         1.f, 0, x_T, C_, 0, 0, FLAG_NT);

    ln_kernel<<<B_ * T_, 256>>>(xb, h2, t_ln2_w, t_ln2_b, C_);

    gemm(h2, C_, 0, 0, ff1_w1, C_, 0, 0, ffb, 4*C_, 0, 0, B_*T_, 4*C_, C_, 1, 1,
         1.f, ff1_b1, 0, 0, 0, 0, FLAG_NT | FLAG_RELU);
    gemm(ffb, 4*C_, 0, 0, ff1_w2, 4*C_, 0, 0, tout, C_, 0, 0, B_*T_, C_, 4*C_, 1, 1,
         1.f, ff1_b2, xb, C_, 0, 0, FLAG_NT);

    // ---- spatial branch ----
    ln_kernel<<<B_ * C_, 256>>>(x_S, hs, s_ln1_w, s_ln1_b, T_);

    gemm(hs, T_, 0, 0, Wq_s, T_, 0, 0, qs, T_, 0, 0, B_*C_, T_, T_, 1, 1,
         1.f, 0, 0, 0, 0, 0, FLAG_NT);
    gemm(hs, T_, 0, 0, Wk_s, T_, 0, 0, ks, T_, 0, 0, B_*C_, T_, T_, 1, 1,
         1.f, 0, 0, 0, 0, 0, FLAG_NT);

    gemm(qs, T_, (long long)C_*T_, HSS, ks, T_, (long long)C_*T_, HSS,
         scS, C_, (long long)H_*CC, CC,
         C_, C_, HSS, B_, H_,
         0.125f, 0, 0, 0, 0, 0, FLAG_NT);

    softmax_kernel<<<B_ * H_ * C_, 256>>>(scS, C_);
    mean_heads_kernel<<<(B_*C_*C_ + 255) / 256, 256>>>(scS, sw);

    // ---- fusion ----
    gemm(tout, C_, TC, 0, sw, C_, CC, 0,
         x2b, C_, TC, 0,
         T_, C_, C_, B_, 1,
         1.f, 0, tout, C_, TC, 0, FLAG_NT);

    ln_kernel<<<B_ * T_, 256>>>(x2b, h3, fus_ln_w, fus_ln_b, C_);

    gemm(h3, C_, 0, 0, ff2_w1, C_, 0, 0, ffb, 4*C_, 0, 0, B_*T_, 4*C_, C_, 1, 1,
         1.f, ff2_b1, 0, 0, 0, 0, FLAG_NT | FLAG_RELU);
    gemm(ffb, 4*C_, 0, 0, ff2_w2, 4*C_, 0, 0, out, C_, 0, 0, B_*T_, C_, 4*C_, 1, 1,
         1.f, ff2_b2, x2b, C_, 0, 0, FLAG_NT);
}

// round 10
// speedup vs baseline: 1.5452x; 1.4489x over previous
#include <cuda_runtime.h>
#include <cuda_bf16.h>
#include <math.h>

#define B_  16
#define T_  512
#define C_  256
#define H_  8
#define HST 32
#define HSS 64

#define N_BTC (B_*T_*C_)
#define N_FF  (B_*T_*4*C_)
#define N_SCT ((long long)B_*H_*T_*T_)
#define N_SCS ((long long)B_*H_*C_*C_)

#define O_h    0
#define O_q    (O_h    + N_BTC)
#define O_k    (O_q    + N_BTC)
#define O_v    (O_k    + N_BTC)
#define O_o    (O_v    + N_BTC)
#define O_x    (O_o    + N_BTC)
#define O_h2   (O_x    + N_BTC)
#define O_tout (O_h2   + N_BTC)
#define O_hs   (O_tout + N_BTC)
#define O_qs   (O_hs   + N_BTC)
#define O_ks   (O_qs   + N_BTC)
#define O_x2   (O_ks   + N_BTC)
#define O_h3   (O_x2   + N_BTC)
#define O_ff   (O_h3   + N_BTC)
#define O_scT  (O_ff   + N_FF)
#define O_scS  (O_scT  + N_SCT)
#define TOTAL_SCRATCH (O_scS + N_SCS)

__device__ float g_buf[TOTAL_SCRATCH];

// ============================== LayerNorm ==================================
__global__ void ln_kernel(const float* __restrict__ x, float* __restrict__ y,
                          const float* __restrict__ w, const float* __restrict__ b,
                          int L) {
    long long base = (long long)blockIdx.x * L;
    int tid = threadIdx.x;
    float s = 0.f, s2 = 0.f;
    for (int i = tid; i < L; i += 256) {
        float v = x[base + i];
        s += v; s2 += v * v;
    }
    __shared__ float sh[64];
    #pragma unroll
    for (int o = 16; o > 0; o >>= 1) {
        s  += __shfl_down_sync(0xffffffffu, s,  o);
        s2 += __shfl_down_sync(0xffffffffu, s2, o);
    }
    int warp = tid >> 5, lane = tid & 31;
    if (lane == 0) { sh[warp] = s; sh[warp + 32] = s2; }
    __syncthreads();
    if (tid == 0) {
        float ts = 0.f, ts2 = 0.f;
        for (int i = 0; i < 8; i++) { ts += sh[i]; ts2 += sh[32 + i]; }
        float m = ts / (float)L;
        float var = ts2 / (float)L - m * m;
        sh[0] = m;
        sh[1] = rsqrtf(var + 1e-6f);
    }
    __syncthreads();
    float m = sh[0], r = sh[1];
    for (int i = tid; i < L; i += 256)
        y[base + i] = (x[base + i] - m) * r * w[i] + b[i];
}

// ===================== Softmax (full row, length L<=512) ===================
__global__ void softmax_kernel(float* __restrict__ x, int L) {
    long long base = (long long)blockIdx.x * L;
    int tid = threadIdx.x;
    float v[2];
    #pragma unroll
    for (int c = 0; c < 2; c++) {
        int i = tid + c * 256;
        v[c] = (i < L) ? x[base + i] : -3.4e38f;
    }
    float mx = fmaxf(v[0], v[1]);
    __shared__ float sh[32];
    #pragma unroll
    for (int o = 16; o > 0; o >>= 1) mx = fmaxf(mx, __shfl_down_sync(0xffffffffu, mx, o));
    int warp = tid >> 5, lane = tid & 31;
    if (lane == 0) sh[warp] = mx;
    __syncthreads();
    if (tid == 0) {
        float m = sh[0];
        for (int i = 1; i < 8; i++) m = fmaxf(m, sh[i]);
        sh[0] = m;
    }
    __syncthreads();
    mx = sh[0];
    float sum = 0.f;
    #pragma unroll
    for (int c = 0; c < 2; c++) {
        int i = tid + c * 256;
        if (i < L) { v[c] = expf(v[c] - mx); sum += v[c]; }
    }
    __syncthreads();
    #pragma unroll
    for (int o = 16; o > 0; o >>= 1) sum += __shfl_down_sync(0xffffffffu, sum, o);
    if (lane == 0) sh[warp] = sum;
    __syncthreads();
    if (tid == 0) {
        float s = 0.f;
        for (int i = 0; i < 8; i++) s += sh[i];
        sh[0] = 1.f / s;
    }
    __syncthreads();
    float inv = sh[0];
    #pragma unroll
    for (int c = 0; c < 2; c++) {
        int i = tid + c * 256;
        if (i < L) x[base + i] = v[c] * inv;
    }
}

// ============== Causal softmax over rows of length T_ (=512) ===============
__global__ void softmax_causal_kernel(float* __restrict__ x) {
    long long base = (long long)blockIdx.x * T_;
    int t = blockIdx.x % T_;
    int tid = threadIdx.x;
    float v[2];
    bool act[2];
    #pragma unroll
    for (int c = 0; c < 2; c++) {
        int i = tid + c * 256;
        act[c] = (i <= t);
        v[c] = act[c] ? x[base + i] : -3.4e38f;
    }
    float mx = fmaxf(v[0], v[1]);
    __shared__ float sh[32];
    #pragma unroll
    for (int o = 16; o > 0; o >>= 1) mx = fmaxf(mx, __shfl_down_sync(0xffffffffu, mx, o));
    int warp = tid >> 5, lane = tid & 31;
    if (lane == 0) sh[warp] = mx;
    __syncthreads();
    if (tid == 0) {
        float m = sh[0];
        for (int i = 1; i < 8; i++) m = fmaxf(m, sh[i]);
        sh[0] = m;
    }
    __syncthreads();
    mx = sh[0];
    float sum = 0.f;
    #pragma unroll
    for (int c = 0; c < 2; c++) {
        if (act[c]) { v[c] = expf(v[c] - mx); sum += v[c]; }
    }
    __syncthreads();
    #pragma unroll
    for (int o = 16; o > 0; o >>= 1) sum += __shfl_down_sync(0xffffffffu, sum, o);
    if (lane == 0) sh[warp] = sum;
    __syncthreads();
    if (tid == 0) {
        float s = 0.f;
        for (int i = 0; i < 8; i++) s += sh[i];
        sh[0] = 1.f / s;
    }
    __syncthreads();
    float inv = sh[0];
    #pragma unroll
    for (int c = 0; c < 2; c++) {
        int i = tid + c * 256;
        x[base + i] = act[c] ? v[c] * inv : 0.f;
    }
}

// ============================ Mean over heads ==============================
__global__ void mean_heads_kernel(const float* __restrict__ sc, float* __restrict__ out) {
    long long idx = (long long)blockIdx.x * 256 + threadIdx.x;
    const long long NN = (long long)B_ * C_ * C_;
    if (idx >= NN) return;
    long long b = idx / (C_ * C_);
    long long r = idx % (C_ * C_);
    float s = 0.f;
    #pragma unroll
    for (int h = 0; h < H_; h++)
        s += sc[(b * H_ + h) * (long long)(C_ * C_) + r];
    out[idx] = s * 0.125f;
}

// ================= Pipelined tensor-core GEMM (3x BF16) ====================
#define FLAG_RELU    1
#define FLAG_NT      4
#define FLAG_TRISKIP 8
#define FLAG_KTRI    16

__device__ __forceinline__ void split2(float x0, float x1, unsigned &hi, unsigned &lo) {
    __nv_bfloat162 h = __floats2bfloat162_rn(x0, x1);
    float r0 = x0 - __bfloat162float(h.x);
    float r1 = x1 - __bfloat162float(h.y);
    __nv_bfloat162 l = __floats2bfloat162_rn(r0, r1);
    hi = *reinterpret_cast<unsigned*>(&h);
    lo = *reinterpret_cast<unsigned*>(&l);
}
__device__ __forceinline__ void mma16(float* c, const unsigned* a, const unsigned* b) {
    asm volatile("mma.sync.aligned.m16n8k16.row.col.f32.bf16.bf16.f32 "
        "{%0,%1,%2,%3}, {%4,%5,%6,%7}, {%8,%9}, {%0,%1,%2,%3};"
        : "+f"(c[0]), "+f"(c[1]), "+f"(c[2]), "+f"(c[3])
        : "r"(a[0]), "r"(a[1]), "r"(a[2]), "r"(a[3]), "r"(b[0]), "r"(b[1]));
}
// swizzle: column c of k-pair row kp stored at c ^ ((kp>>1 & 7)<<2)
__device__ __forceinline__ int SWZ(int kp, int c) { return c ^ (((kp >> 1) & 7) << 2); }

template<int BN, int WN, int MINB>
__global__ __launch_bounds__(128 * WN, MINB)
void mma_gemm(const float* __restrict__ A, int lda, long long sAo, long long sAi, int nInner,
              const float* __restrict__ Bm, int ldb, long long sBo, long long sBi,
              float* __restrict__ Cm, int ldc, long long sCo, long long sCi,
              int K, float alpha,
              const float* __restrict__ bias,
              const float* __restrict__ res, int ldres, long long sRo, long long sRi,
              int flags) {
    constexpr int BM = 128, BK = 32;
    constexpr int THREADS = 128 * WN;
    constexpr int WNT = BN / WN;
    constexpr int NJ  = WNT / 8;
    constexpr int BMP = BM + 8, BNP = BN + 8;
    constexpr int AH_O = 0;
    constexpr int AL_O = 16 * BMP;
    constexpr int BH_O = 32 * BMP;
    constexpr int BL_O = 32 * BMP + 16 * BNP;
    constexpr int STG  = 32 * (BMP + BNP);
    constexpr int AITER = (BM * 8) / THREADS;
    constexpr int BITER = (BN * 8) / THREADS;

    int row0 = blockIdx.y * BM;
    int col0 = blockIdx.x * BN;
    if ((flags & FLAG_TRISKIP) && col0 > row0 + BM - 1) return;

    extern __shared__ unsigned sm[];

    int z  = blockIdx.z;
    int zo = z / nInner, zi = z % nInner;
    const float* Ab = A  + zo * sAo + zi * sAi;
    const float* Bb = Bm + zo * sBo + zi * sBi;
    float*       Cb = Cm + zo * sCo + zi * sCi;
    const float* Rb = res ? (res + zo * sRo + zi * sRi) : (const float*)0;

    int tid = threadIdx.x, lane = tid & 31, wid = tid >> 5;
    int wm = wid & 3, wn = wid >> 2;
    int r = lane >> 2, cq = lane & 3;
    bool nt = (flags & FLAG_NT) != 0;

    int Keff = (flags & FLAG_KTRI) ? min(K, row0 + BM) : K;
    int nk = Keff / BK;

    float4 ra[AITER], rb[BITER];

    auto loadT = [&](int k0) {
        #pragma unroll
        for (int i = 0; i < AITER; i++) {
            int idx = tid + i * THREADS;
            int m = idx >> 3, k4 = idx & 7;
            ra[i] = *reinterpret_cast<const float4*>(
                Ab + (long long)(row0 + m) * lda + k0 + k4 * 4);
        }
        if (nt) {
            #pragma unroll
            for (int i = 0; i < BITER; i++) {
                int idx = tid + i * THREADS;
                int n = idx >> 3, k4 = idx & 7;
                rb[i] = *reinterpret_cast<const float4*>(
                    Bb + (long long)(col0 + n) * ldb + k0 + k4 * 4);
            }
        } else {
            #pragma unroll
            for (int i = 0; i < BITER; i++) {
                #pragma unroll
                for (int pz = 0; pz < 2; pz++) {
                    int pidx = tid + (i * 2 + pz) * THREADS;
                    int kk2 = pidx / BN;
                    int n = pidx % BN;
                    const float* bp = Bb + (long long)(k0 + kk2 * 2) * ldb + col0 + n;
                    float b0 = bp[0], b1 = bp[ldb];
                    if (pz == 0) { rb[i].x = b0; rb[i].y = b1; }
                    else         { rb[i].z = b0; rb[i].w = b1; }
                }
            }
        }
    };

    auto storeT = [&](int s) {
        unsigned* ah = sm + s * STG + AH_O;
        unsigned* al = sm + s * STG + AL_O;
        unsigned* bh = sm + s * STG + BH_O;
        unsigned* bl = sm + s * STG + BL_O;
        #pragma unroll
        for (int i = 0; i < AITER; i++) {
            int idx = tid + i * THREADS;
            int m = idx >> 3, k4 = idx & 7;
            int mc = m ^ (k4 << 2);
            unsigned h0, l0, h1, l1;
            split2(ra[i].x, ra[i].y, h0, l0);
            split2(ra[i].z, ra[i].w, h1, l1);
            ah[(k4 * 2) * BMP + mc] = h0;     al[(k4 * 2) * BMP + mc] = l0;
            ah[(k4 * 2 + 1) * BMP + mc] = h1; al[(k4 * 2 + 1) * BMP + mc] = l1;
        }
        if (nt) {
            #pragma unroll
            for (int i = 0; i < BITER; i++) {
                int idx = tid + i * THREADS;
                int n = idx >> 3, k4 = idx & 7;
                int nc = n ^ (k4 << 2);
                unsigned h0, l0, h1, l1;
                split2(rb[i].x, rb[i].y, h0, l0);
                split2(rb[i].z, rb[i].w, h1, l1);
                bh[(k4 * 2) * BNP + nc] = h0;     bl[(k4 * 2) * BNP + nc] = l0;
                bh[(k4 * 2 + 1) * BNP + nc] = h1; bl[(k4 * 2 + 1) * BNP + nc] = l1;
            }
        } else {
            #pragma unroll
            for (int i = 0; i < BITER; i++) {
                #pragma unroll
                for (int pz = 0; pz < 2; pz++) {
                    int pidx = tid + (i * 2 + pz) * THREADS;
                    int kk2 = pidx / BN;
                    int n = pidx % BN;
                    int nc = SWZ(kk2, n);
                    float b0 = pz ? rb[i].z : rb[i].x;
                    float b1 = pz ? rb[i].w : rb[i].y;
                    unsigned h0, l0;
                    split2(b0, b1, h0, l0);
                    bh[kk2 * BNP + nc] = h0;
                    bl[kk2 * BNP + nc] = l0;
                }
            }
        }
    };

    float acc[2][NJ][4];
    #pragma unroll
    for (int i = 0; i < 2; i++)
        #pragma unroll
        for (int j = 0; j < NJ; j++)
            #pragma unroll
            for (int e = 0; e < 4; e++) acc[i][j][e] = 0.f;

    auto compute = [&](int s) {
        const unsigned* ah = sm + s * STG + AH_O;
        const unsigned* al = sm + s * STG + AL_O;
        const unsigned* bhp = sm + s * STG + BH_O;
        const unsigned* blp = sm + s * STG + BL_O;
        #pragma unroll
        for (int k16 = 0; k16 < 2; k16++) {
            int kp0 = k16 * 8 + cq, kp1 = kp0 + 4;
            unsigned bf_h[NJ][2], bf_l[NJ][2];
            #pragma unroll
            for (int j = 0; j < NJ; j++) {
                int ncol = wn * WNT + j * 8 + r;
                bf_h[j][0] = bhp[kp0 * BNP + SWZ(kp0, ncol)];
                bf_h[j][1] = bhp[kp1 * BNP + SWZ(kp1, ncol)];
                bf_l[j][0] = blp[kp0 * BNP + SWZ(kp0, ncol)];
                bf_l[j][1] = blp[kp1 * BNP + SWZ(kp1, ncol)];
            }
            #pragma unroll
            for (int im = 0; im < 2; im++) {
                int mrow = wm * 32 + im * 16 + r;
                unsigned afh[4], afl[4];
                afh[0] = ah[kp0 * BMP + SWZ(kp0, mrow)];
                afh[1] = ah[kp0 * BMP + SWZ(kp0, mrow + 8)];
                afh[2] = ah[kp1 * BMP + SWZ(kp1, mrow)];
                afh[3] = ah[kp1 * BMP + SWZ(kp1, mrow + 8)];
                afl[0] = al[kp0 * BMP + SWZ(kp0, mrow)];
                afl[1] = al[kp0 * BMP + SWZ(kp0, mrow + 8)];
                afl[2] = al[kp1 * BMP + SWZ(kp1, mrow)];
                afl[3] = al[kp1 * BMP + SWZ(kp1, mrow + 8)];
                #pragma unroll
                for (int j = 0; j < NJ; j++) {
                    mma16(acc[im][j], afl, bf_h[j]);
                    mma16(acc[im][j], afh, bf_l[j]);
                    mma16(acc[im][j], afh, bf_h[j]);
                }
            }
        }
    };

    // ---- pipelined mainloop: 1 sync per iteration, double-buffered ----
    loadT(0);
    storeT(0);
    int p = 0;
    for (int kb = 0; kb < nk; kb++) {
        __syncthreads();
        bool more = (kb + 1) < nk;
        if (more) loadT((kb + 1) * BK);
        compute(p);
        if (more) storeT(1 - p);
        p ^= 1;
    }

    // ---- epilogue ----
    #pragma unroll
    for (int im = 0; im < 2; im++) {
        #pragma unroll
        for (int j = 0; j < NJ; j++) {
            int gm0 = row0 + wm * 32 + im * 16 + r;
            int gn  = col0 + wn * WNT + j * 8 + cq * 2;
            #pragma unroll
            for (int half = 0; half < 2; half++) {
                int gm = gm0 + half * 8;
                float v0 = acc[im][j][half * 2 + 0] * alpha;
                float v1 = acc[im][j][half * 2 + 1] * alpha;
                if (bias) { v0 += bias[gn]; v1 += bias[gn + 1]; }
                if (flags & FLAG_RELU) { v0 = fmaxf(v0, 0.f); v1 = fmaxf(v1, 0.f); }
                if (Rb) {
                    const float* rp = Rb + (long long)gm * ldres + gn;
                    v0 += rp[0]; v1 += rp[1];
                }
                float2 st; st.x = v0; st.y = v1;
                *reinterpret_cast<float2*>(Cb + (long long)gm * ldc + gn) = st;
            }
        }
    }
}

#define SMEM_BYTES(BN) (2 * 32 * ((128 + 8) + ((BN) + 8)) * 4)

static inline void gemm(const float* A, int lda, long long sAo, long long sAi,
                        const float* Bm, int ldb, long long sBo, long long sBi,
                        float* Cm, int ldc, long long sCo, long long sCi,
                        int M, int N, int K, int bOuter, int bInner,
                        float alpha, const float* bias,
                        const float* res, int ldres, long long sRo, long long sRi,
                        int flags) {
    if (N == 32) {
        dim3 grid(1, M / 128, bOuter * bInner);
        mma_gemm<32, 1, 2><<<grid, 128, SMEM_BYTES(32)>>>(
            A, lda, sAo, sAi, bInner, Bm, ldb, sBo, sBi, Cm, ldc, sCo, sCi,
            K, alpha, bias, res, ldres, sRo, sRi, flags);
    } else {
        dim3 grid(N / 64, M / 128, bOuter * bInner);
        mma_gemm<64, 2, 2><<<grid, 256, SMEM_BYTES(64)>>>(
            A, lda, sAo, sAi, bInner, Bm, ldb, sBo, sBi, Cm, ldc, sCo, sCi,
            K, alpha, bias, res, ldres, sRo, sRi, flags);
    }
}

// ================================ Launch ===================================
extern "C" void kernel_launch(void* const* d_in, const int* in_sizes, int n_in,
                              void* d_out, int out_size) {
    static int smem_cfg = 0;
    if (!smem_cfg) {
        cudaFuncSetAttribute((const void*)mma_gemm<64, 2, 2>,
                             cudaFuncAttributeMaxDynamicSharedMemorySize, SMEM_BYTES(64));
        cudaFuncSetAttribute((const void*)mma_gemm<32, 1, 2>,
                             cudaFuncAttributeMaxDynamicSharedMemorySize, SMEM_BYTES(32));
        smem_cfg = 1;
    }

    const float* x_T     = (const float*)d_in[0];
    const float* x_S     = (const float*)d_in[1];
    const float* Wq_t    = (const float*)d_in[2];
    const float* Wk_t    = (const float*)d_in[3];
    const float* Wv_t    = (const float*)d_in[4];
    const float* Wo      = (const float*)d_in[5];
    const float* Wq_s    = (const float*)d_in[6];
    const float* Wk_s    = (const float*)d_in[7];
    const float* ff1_w1  = (const float*)d_in[8];
    const float* ff1_b1  = (const float*)d_in[9];
    const float* ff1_w2  = (const float*)d_in[10];
    const float* ff1_b2  = (const float*)d_in[11];
    const float* ff2_w1  = (const float*)d_in[12];
    const float* ff2_b1  = (const float*)d_in[13];
    const float* ff2_w2  = (const float*)d_in[14];
    const float* ff2_b2  = (const float*)d_in[15];
    const float* t_ln1_w = (const float*)d_in[16];
    const float* t_ln1_b = (const float*)d_in[17];
    const float* t_ln2_w = (const float*)d_in[18];
    const float* t_ln2_b = (const float*)d_in[19];
    const float* s_ln1_w = (const float*)d_in[20];
    const float* s_ln1_b = (const float*)d_in[21];
    const float* fus_ln_w= (const float*)d_in[22];
    const float* fus_ln_b= (const float*)d_in[23];

    float* out = (float*)d_out;                 // [B,T,C]
    float* sw  = out + (size_t)N_BTC;           // [B,C,C]

    float* g = 0;
    cudaGetSymbolAddress((void**)&g, g_buf);
    float* h    = g + O_h;
    float* q    = g + O_q;
    float* k    = g + O_k;
    float* v    = g + O_v;
    float* ob   = g + O_o;
    float* xb   = g + O_x;
    float* h2   = g + O_h2;
    float* tout = g + O_tout;
    float* hs   = g + O_hs;
    float* qs   = g + O_qs;
    float* ks   = g + O_ks;
    float* x2b  = g + O_x2;
    float* h3   = g + O_h3;
    float* ffb  = g + O_ff;
    float* scT  = g + O_scT;
    float* scS  = g + O_scS;

    const long long TC = (long long)T_ * C_;
    const long long TT = (long long)T_ * T_;
    const long long CC = (long long)C_ * C_;

    // ---- temporal branch ----
    ln_kernel<<<B_ * T_, 256>>>(x_T, h, t_ln1_w, t_ln1_b, C_);

    gemm(h, C_, 0, 0, Wq_t, C_, 0, 0, q, C_, 0, 0, B_*T_, C_, C_, 1, 1,
         1.f, 0, 0, 0, 0, 0, FLAG_NT);
    gemm(h, C_, 0, 0, Wk_t, C_, 0, 0, k, C_, 0, 0, B_*T_, C_, C_, 1, 1,
         1.f, 0, 0, 0, 0, 0, FLAG_NT);
    gemm(h, C_, 0, 0, Wv_t, C_, 0, 0, v, C_, 0, 0, B_*T_, C_, C_, 1, 1,
         1.f, 0, 0, 0, 0, 0, FLAG_NT);

    gemm(q, C_, TC, HST, k, C_, TC, HST,
         scT, T_, (long long)H_*TT, TT,
         T_, T_, HST, B_, H_,
         0.1767766952966369f, 0, 0, 0, 0, 0, FLAG_NT | FLAG_TRISKIP);

    softmax_causal_kernel<<<B_ * H_ * T_, 256>>>(scT);

    gemm(scT, T_, (long long)H_*TT, TT, v, C_, TC, HST,
         ob, C_, TC, HST,
         T_, HST, T_, B_, H_,
         1.f, 0, 0, 0, 0, 0, FLAG_KTRI);

    gemm(ob, C_, 0, 0, Wo, C_, 0, 0, xb, C_, 0, 0, B_*T_, C_, C_, 1, 1,
         1.f, 0, x_T, C_, 0, 0, FLAG_NT);

    ln_kernel<<<B_ * T_, 256>>>(xb, h2, t_ln2_w, t_ln2_b, C_);

    gemm(h2, C_, 0, 0, ff1_w1, C_, 0, 0, ffb, 4*C_, 0, 0, B_*T_, 4*C_, C_, 1, 1,
         1.f, ff1_b1, 0, 0, 0, 0, FLAG_NT | FLAG_RELU);
    gemm(ffb, 4*C_, 0, 0, ff1_w2, 4*C_, 0, 0, tout, C_, 0, 0, B_*T_, C_, 4*C_, 1, 1,
         1.f, ff1_b2, xb, C_, 0, 0, FLAG_NT);

    // ---- spatial branch ----
    ln_kernel<<<B_ * C_, 256>>>(x_S, hs, s_ln1_w, s_ln1_b, T_);

    gemm(hs, T_, 0, 0, Wq_s, T_, 0, 0, qs, T_, 0, 0, B_*C_, T_, T_, 1, 1,
         1.f, 0, 0, 0, 0, 0, FLAG_NT);
    gemm(hs, T_, 0, 0, Wk_s, T_, 0, 0, ks, T_, 0, 0, B_*C_, T_, T_, 1, 1,
         1.f, 0, 0, 0, 0, 0, FLAG_NT);

    gemm(qs, T_, (long long)C_*T_, HSS, ks, T_, (long long)C_*T_, HSS,
         scS, C_, (long long)H_*CC, CC,
         C_, C_, HSS, B_, H_,
         0.125f, 0, 0, 0, 0, 0, FLAG_NT);

    softmax_kernel<<<B_ * H_ * C_, 256>>>(scS, C_);
    mean_heads_kernel<<<(B_*C_*C_ + 255) / 256, 256>>>(scS, sw);

    // ---- fusion ----
    gemm(tout, C_, TC, 0, sw, C_, CC, 0,
         x2b, C_, TC, 0,
         T_, C_, C_, B_, 1,
         1.f, 0, tout, C_, TC, 0, FLAG_NT);

    ln_kernel<<<B_ * T_, 256>>>(x2b, h3, fus_ln_w, fus_ln_b, C_);

    gemm(h3, C_, 0, 0, ff2_w1, C_, 0, 0, ffb, 4*C_, 0, 0, B_*T_, 4*C_, C_, 1, 1,
         1.f, ff2_b1, 0, 0, 0, 0, FLAG_NT | FLAG_RELU);
    gemm(ffb, 4*C_, 0, 0, ff2_w2, 4*C_, 0, 0, out, C_, 0, 0, B_*T_, C_, 4*C_, 1, 1,
         1.f, ff2_b2, x2b, C_, 0, 0, FLAG_NT);
}